// round 7
// baseline (speedup 1.0000x reference)
#include <cuda_runtime.h>
#include <math.h>

// Problem shape (fixed by dataset): h (B=4, T=4096, d=512) fp32, raw_alpha (K=4) fp32
// out: (B, T, K, d) fp32
#define T_DIM 4096
#define D_DIM 512
#define K_DIM 4
#define B_MAX 4
#define CHUNK_L 16
#define NCHUNK (T_DIM / CHUNK_L)   // 256

// Scratch (allocation-free: __device__ globals)
__device__ float  g_rtab[T_DIM * K_DIM];                       // r[t][k] = (1-a)/(1-a^{t+1})
__device__ float4 g_alpha4;                                    // alpha per k
__device__ float4 g_powL4;                                     // alpha^CHUNK_L per k
__device__ float  g_E[B_MAX * NCHUNK * D_DIM * K_DIM];         // chunk-end sums -> carries (in place), 8MB

__device__ __forceinline__ double sigmoid_clip_d(double x) {
    double a = 1.0 / (1.0 + exp(-x));
    a = fmin(fmax(a, 1e-6), 1.0 - 1e-6);
    return a;
}

// ---------------------------------------------------------------------------
// Kernel A: tables (double precision, one thread per t)
// ---------------------------------------------------------------------------
__global__ void kA_tables(const float* __restrict__ raw_alpha) {
    int t = blockIdx.x * blockDim.x + threadIdx.x;
    if (t >= T_DIM) return;

    double a[K_DIM], la[K_DIM];
#pragma unroll
    for (int k = 0; k < K_DIM; k++) {
        a[k]  = sigmoid_clip_d((double)raw_alpha[k]);
        la[k] = log(a[k]);
    }
#pragma unroll
    for (int k = 0; k < K_DIM; k++) {
        double p = exp(la[k] * (double)(t + 1));   // alpha^{t+1} (underflow to 0 fine)
        double r = (1.0 - a[k]) / (1.0 - p);
        g_rtab[t * K_DIM + k] = (float)r;
    }
    if (t == 0) {
        g_alpha4 = make_float4((float)a[0], (float)a[1], (float)a[2], (float)a[3]);
        g_powL4  = make_float4((float)exp(la[0] * (double)CHUNK_L),
                               (float)exp(la[1] * (double)CHUNK_L),
                               (float)exp(la[2] * (double)CHUNK_L),
                               (float)exp(la[3] * (double)CHUNK_L));
    }
}

// ---------------------------------------------------------------------------
// Kernel B: per-chunk local scans -> chunk-end sums E[b][c][dd][k]
// Thread handles (b, c, dd4): 4 consecutive d-lanes x 4 k-channels in regs.
// ---------------------------------------------------------------------------
__global__ __launch_bounds__(256) void kB_chunks(const float* __restrict__ h, int Bn) {
    const int DV  = D_DIM / 4;
    int tid = blockIdx.x * blockDim.x + threadIdx.x;
    int ddv = tid % DV;
    int c   = (tid / DV) % NCHUNK;
    int b   = tid / (DV * NCHUNK);
    if (b >= Bn) return;
    int dd = ddv * 4;

    const float4 a4 = g_alpha4;
    float4 S0 = make_float4(0.f, 0.f, 0.f, 0.f);
    float4 S1 = S0, S2 = S0, S3 = S0;

    const float4* hp = (const float4*)(h + ((size_t)b * T_DIM + (size_t)c * CHUNK_L) * D_DIM + dd);

#pragma unroll
    for (int j = 0; j < CHUNK_L; j++) {
        float4 h4 = hp[(size_t)j * DV];
        S0.x = fmaf(a4.x, S0.x, h4.x); S0.y = fmaf(a4.y, S0.y, h4.x);
        S0.z = fmaf(a4.z, S0.z, h4.x); S0.w = fmaf(a4.w, S0.w, h4.x);
        S1.x = fmaf(a4.x, S1.x, h4.y); S1.y = fmaf(a4.y, S1.y, h4.y);
        S1.z = fmaf(a4.z, S1.z, h4.y); S1.w = fmaf(a4.w, S1.w, h4.y);
        S2.x = fmaf(a4.x, S2.x, h4.z); S2.y = fmaf(a4.y, S2.y, h4.z);
        S2.z = fmaf(a4.z, S2.z, h4.z); S2.w = fmaf(a4.w, S2.w, h4.z);
        S3.x = fmaf(a4.x, S3.x, h4.w); S3.y = fmaf(a4.y, S3.y, h4.w);
        S3.z = fmaf(a4.z, S3.z, h4.w); S3.w = fmaf(a4.w, S3.w, h4.w);
    }

    float4* Ep = (float4*)&g_E[(((size_t)b * NCHUNK + c) * D_DIM + dd) * K_DIM];
    Ep[0] = S0; Ep[1] = S1; Ep[2] = S2; Ep[3] = S3;
}

// ---------------------------------------------------------------------------
// Kernel C: inter-chunk affine scan, in place: E[b][c][dd][k] becomes the
// carry into chunk c (= global scan value at t = c*L - 1; 0 for c = 0).
// Serial dep is a register-only FMA chain; loads are independent.
// ---------------------------------------------------------------------------
__global__ __launch_bounds__(256) void kC_scan(int Bn) {
    int tid = blockIdx.x * blockDim.x + threadIdx.x;
    int dd  = tid % D_DIM;
    int b   = tid / D_DIM;
    if (b >= Bn) return;

    const float4 pl = g_powL4;
    float4 prev = make_float4(0.f, 0.f, 0.f, 0.f);

    for (int c = 0; c < NCHUNK; c++) {
        float4* p = (float4*)&g_E[(((size_t)b * NCHUNK + c) * D_DIM + dd) * K_DIM];
        float4 e = *p;
        *p = prev;                              // carry into chunk c
        prev.x = fmaf(pl.x, prev.x, e.x);
        prev.y = fmaf(pl.y, prev.y, e.y);
        prev.z = fmaf(pl.z, prev.z, e.z);
        prev.w = fmaf(pl.w, prev.w, e.w);
    }
}

// ---------------------------------------------------------------------------
// Kernel D: final scan + normalize + store (streaming stores, write-once data)
// ---------------------------------------------------------------------------
__global__ __launch_bounds__(256) void kD_final(const float* __restrict__ h,
                                                float* __restrict__ out, int Bn) {
    const int DV  = D_DIM / 4;
    int tid = blockIdx.x * blockDim.x + threadIdx.x;
    int ddv = tid % DV;
    int c   = (tid / DV) % NCHUNK;
    int b   = tid / (DV * NCHUNK);
    if (b >= Bn) return;
    int dd = ddv * 4;

    const float4 a4 = g_alpha4;

    const float4* Ep = (const float4*)&g_E[(((size_t)b * NCHUNK + c) * D_DIM + dd) * K_DIM];
    float4 S0 = Ep[0], S1 = Ep[1], S2 = Ep[2], S3 = Ep[3];

    const float*  hp = h + ((size_t)b * T_DIM + (size_t)c * CHUNK_L) * D_DIM + dd;
    float*        op = out + ((size_t)b * T_DIM + (size_t)c * CHUNK_L) * K_DIM * D_DIM + dd;
    const float4* rp = (const float4*)&g_rtab[((size_t)c * CHUNK_L) * K_DIM];

#pragma unroll
    for (int j = 0; j < CHUNK_L; j++) {
        float4 h4 = *(const float4*)(hp + (size_t)j * D_DIM);
        float4 r4 = rp[j];

        S0.x = fmaf(a4.x, S0.x, h4.x); S0.y = fmaf(a4.y, S0.y, h4.x);
        S0.z = fmaf(a4.z, S0.z, h4.x); S0.w = fmaf(a4.w, S0.w, h4.x);
        S1.x = fmaf(a4.x, S1.x, h4.y); S1.y = fmaf(a4.y, S1.y, h4.y);
        S1.z = fmaf(a4.z, S1.z, h4.y); S1.w = fmaf(a4.w, S1.w, h4.y);
        S2.x = fmaf(a4.x, S2.x, h4.z); S2.y = fmaf(a4.y, S2.y, h4.z);
        S2.z = fmaf(a4.z, S2.z, h4.z); S2.w = fmaf(a4.w, S2.w, h4.z);
        S3.x = fmaf(a4.x, S3.x, h4.w); S3.y = fmaf(a4.y, S3.y, h4.w);
        S3.z = fmaf(a4.z, S3.z, h4.w); S3.w = fmaf(a4.w, S3.w, h4.w);

        // transpose in registers: o_k = {S0[k], S1[k], S2[k], S3[k]} * r[k]
        float4 o0 = make_float4(S0.x * r4.x, S1.x * r4.x, S2.x * r4.x, S3.x * r4.x);
        float4 o1 = make_float4(S0.y * r4.y, S1.y * r4.y, S2.y * r4.y, S3.y * r4.y);
        float4 o2 = make_float4(S0.z * r4.z, S1.z * r4.z, S2.z * r4.z, S3.z * r4.z);
        float4 o3 = make_float4(S0.w * r4.w, S1.w * r4.w, S2.w * r4.w, S3.w * r4.w);

        float* ob = op + (size_t)j * K_DIM * D_DIM;
        __stcs((float4*)(ob + 0 * D_DIM), o0);
        __stcs((float4*)(ob + 1 * D_DIM), o1);
        __stcs((float4*)(ob + 2 * D_DIM), o2);
        __stcs((float4*)(ob + 3 * D_DIM), o3);
    }
}

// ---------------------------------------------------------------------------
extern "C" void kernel_launch(void* const* d_in, const int* in_sizes, int n_in,
                              void* d_out, int out_size) {
    // Identify inputs by size (robust to ordering): h has B*T*D elems, raw_alpha has K.
    const float* h         = (const float*)d_in[0];
    const float* raw_alpha = (const float*)d_in[1];
    int h_elems = in_sizes[0];
    if (n_in >= 2 && in_sizes[1] > in_sizes[0]) {
        h         = (const float*)d_in[1];
        raw_alpha = (const float*)d_in[0];
        h_elems   = in_sizes[1];
    }
    float* out = (float*)d_out;

    int Bn = h_elems / (T_DIM * D_DIM);
    if (Bn > B_MAX) Bn = B_MAX;
    if (Bn < 1)     Bn = 1;

    // A: tables
    kA_tables<<<(T_DIM + 255) / 256, 256>>>(raw_alpha);

    // B: chunk-local scans
    {
        int total = Bn * NCHUNK * (D_DIM / 4);
        kB_chunks<<<(total + 255) / 256, 256>>>(h, Bn);
    }

    // C: inter-chunk carry scan (in place)
    {
        int total = Bn * D_DIM;
        kC_scan<<<(total + 255) / 256, 256>>>(Bn);
    }

    // D: final scan + normalize
    {
        int total = Bn * NCHUNK * (D_DIM / 4);
        kD_final<<<(total + 255) / 256, 256>>>(h, out, Bn);
    }
}

// round 9
// speedup vs baseline: 1.2614x; 1.2614x over previous
#include <cuda_runtime.h>
#include <math.h>

// h (B=4, T=4096, d=512) fp32, raw_alpha (K=4) fp32 -> out (B, T, K, d) fp32
#define T_DIM 4096
#define D_DIM 512
#define K_DIM 4
#define B_MAX 4
#define CHUNK_L 16
#define NCHUNK (T_DIM / CHUNK_L)   // 256
#define GROUP 16
#define NGROUP (NCHUNK / GROUP)    // 16

// Scratch (allocation-free: __device__ globals)
__device__ float  g_rtab[T_DIM * K_DIM];                    // r[t][k]
__device__ float4 g_alpha4;                                 // alpha
__device__ float4 g_powL4;                                  // q = alpha^16
__device__ float4 g_powLL4;                                 // Q = alpha^256
__device__ float4 g_qpow[GROUP];                            // q^i, i=0..15
__device__ float  g_E[B_MAX * NCHUNK * D_DIM * K_DIM];      // chunk sums -> local carries (8MB)
__device__ float  g_G[B_MAX * NGROUP * D_DIM * K_DIM];      // group sums -> group carries (512KB)

__device__ __forceinline__ double sigmoid_clip_d(double x) {
    double a = 1.0 / (1.0 + exp(-x));
    return fmin(fmax(a, 1e-6), 1.0 - 1e-6);
}

// ---------------------------------------------------------------------------
// kA: tables (double precision, one thread per t)
// ---------------------------------------------------------------------------
__global__ void kA_tables(const float* __restrict__ raw_alpha) {
    int t = blockIdx.x * blockDim.x + threadIdx.x;
    if (t >= T_DIM) return;

    double a[K_DIM], la[K_DIM];
#pragma unroll
    for (int k = 0; k < K_DIM; k++) {
        a[k]  = sigmoid_clip_d((double)raw_alpha[k]);
        la[k] = log(a[k]);
    }
#pragma unroll
    for (int k = 0; k < K_DIM; k++) {
        double p = exp(la[k] * (double)(t + 1));
        g_rtab[t * K_DIM + k] = (float)((1.0 - a[k]) / (1.0 - p));
    }
    if (t < GROUP) {   // q^t table
        g_qpow[t] = make_float4((float)exp(la[0] * (double)(CHUNK_L * t)),
                                (float)exp(la[1] * (double)(CHUNK_L * t)),
                                (float)exp(la[2] * (double)(CHUNK_L * t)),
                                (float)exp(la[3] * (double)(CHUNK_L * t)));
    }
    if (t == 0) {
        g_alpha4 = make_float4((float)a[0], (float)a[1], (float)a[2], (float)a[3]);
        g_powL4  = make_float4((float)exp(la[0] * (double)CHUNK_L),
                               (float)exp(la[1] * (double)CHUNK_L),
                               (float)exp(la[2] * (double)CHUNK_L),
                               (float)exp(la[3] * (double)CHUNK_L));
        g_powLL4 = make_float4((float)exp(la[0] * (double)(CHUNK_L * GROUP)),
                               (float)exp(la[1] * (double)(CHUNK_L * GROUP)),
                               (float)exp(la[2] * (double)(CHUNK_L * GROUP)),
                               (float)exp(la[3] * (double)(CHUNK_L * GROUP)));
    }
}

// ---------------------------------------------------------------------------
// kB: per-chunk local scans -> chunk sums E[b][c][dd][k]
// Thread: (b, c, dd4) — 4 d-lanes x 4 k in regs.
// ---------------------------------------------------------------------------
__global__ __launch_bounds__(256) void kB_chunks(const float* __restrict__ h, int Bn) {
    const int DV  = D_DIM / 4;
    int tid = blockIdx.x * blockDim.x + threadIdx.x;
    int ddv = tid % DV;
    int c   = (tid / DV) % NCHUNK;
    int b   = tid / (DV * NCHUNK);
    if (b >= Bn) return;
    int dd = ddv * 4;

    const float4 a4 = g_alpha4;
    float4 S0 = make_float4(0.f, 0.f, 0.f, 0.f);
    float4 S1 = S0, S2 = S0, S3 = S0;

    const float4* hp = (const float4*)(h + ((size_t)b * T_DIM + (size_t)c * CHUNK_L) * D_DIM + dd);

#pragma unroll
    for (int j = 0; j < CHUNK_L; j++) {
        float4 h4 = hp[(size_t)j * DV];
        S0.x = fmaf(a4.x, S0.x, h4.x); S0.y = fmaf(a4.y, S0.y, h4.x);
        S0.z = fmaf(a4.z, S0.z, h4.x); S0.w = fmaf(a4.w, S0.w, h4.x);
        S1.x = fmaf(a4.x, S1.x, h4.y); S1.y = fmaf(a4.y, S1.y, h4.y);
        S1.z = fmaf(a4.z, S1.z, h4.y); S1.w = fmaf(a4.w, S1.w, h4.y);
        S2.x = fmaf(a4.x, S2.x, h4.z); S2.y = fmaf(a4.y, S2.y, h4.z);
        S2.z = fmaf(a4.z, S2.z, h4.z); S2.w = fmaf(a4.w, S2.w, h4.z);
        S3.x = fmaf(a4.x, S3.x, h4.w); S3.y = fmaf(a4.y, S3.y, h4.w);
        S3.z = fmaf(a4.z, S3.z, h4.w); S3.w = fmaf(a4.w, S3.w, h4.w);
    }

    float4* Ep = (float4*)&g_E[(((size_t)b * NCHUNK + c) * D_DIM + dd) * K_DIM];
    Ep[0] = S0; Ep[1] = S1; Ep[2] = S2; Ep[3] = S3;
}

// ---------------------------------------------------------------------------
// kC_local: scan within each group of 16 chunks. In place: E[c] becomes the
// local carry into chunk c (within its group). Emits group sums to g_G.
// Thread: (b, g, dd) — float4 over k. 32768 threads.
// ---------------------------------------------------------------------------
__global__ __launch_bounds__(256) void kC_local(int Bn) {
    int tid = blockIdx.x * blockDim.x + threadIdx.x;
    int dd  = tid % D_DIM;
    int g   = (tid / D_DIM) % NGROUP;
    int b   = tid / (D_DIM * NGROUP);
    if (b >= Bn) return;

    const float4 q = g_powL4;
    float4 prev = make_float4(0.f, 0.f, 0.f, 0.f);

#pragma unroll
    for (int i = 0; i < GROUP; i++) {
        int c = g * GROUP + i;
        float4* p = (float4*)&g_E[(((size_t)b * NCHUNK + c) * D_DIM + dd) * K_DIM];
        float4 e = *p;
        *p = prev;
        prev.x = fmaf(q.x, prev.x, e.x);
        prev.y = fmaf(q.y, prev.y, e.y);
        prev.z = fmaf(q.z, prev.z, e.z);
        prev.w = fmaf(q.w, prev.w, e.w);
    }
    *(float4*)&g_G[(((size_t)b * NGROUP + g) * D_DIM + dd) * K_DIM] = prev;
}

// ---------------------------------------------------------------------------
// kC_global: scan over the 16 group sums -> group carries, in place.
// Load-all-then-scan so the 16 loads are independent (one latency round).
// ---------------------------------------------------------------------------
__global__ __launch_bounds__(256) void kC_global(int Bn) {
    int tid = blockIdx.x * blockDim.x + threadIdx.x;
    int dd  = tid % D_DIM;
    int b   = tid / D_DIM;
    if (b >= Bn) return;

    const float4 Q = g_powLL4;
    float4 s[NGROUP];
#pragma unroll
    for (int g = 0; g < NGROUP; g++)
        s[g] = *(float4*)&g_G[(((size_t)b * NGROUP + g) * D_DIM + dd) * K_DIM];

    float4 prev = make_float4(0.f, 0.f, 0.f, 0.f);
#pragma unroll
    for (int g = 0; g < NGROUP; g++) {
        *(float4*)&g_G[(((size_t)b * NGROUP + g) * D_DIM + dd) * K_DIM] = prev;
        prev.x = fmaf(Q.x, prev.x, s[g].x);
        prev.y = fmaf(Q.y, prev.y, s[g].y);
        prev.z = fmaf(Q.z, prev.z, s[g].z);
        prev.w = fmaf(Q.w, prev.w, s[g].w);
    }
}

// ---------------------------------------------------------------------------
// kD: final scan + normalize + store. Split-k: thread = (b, c, kh, dd4),
// 2 k-channels x 4 d-lanes. Block = one (b,c), 256 threads. Grid = Bn*NCHUNK.
// S_init = L_c + G_g * q^i.
// ---------------------------------------------------------------------------
__global__ __launch_bounds__(256) void kD_final(const float* __restrict__ h,
                                                float* __restrict__ out, int Bn) {
    int c   = blockIdx.x % NCHUNK;
    int b   = blockIdx.x / NCHUNK;
    if (b >= Bn) return;
    int tid = threadIdx.x;
    int ddv = tid & 127;          // 0..127
    int kh  = tid >> 7;           // 0..1
    int dd  = ddv * 4;
    int g   = c >> 4, i = c & 15;

    const float* ab = (const float*)&g_alpha4;
    float2 a2 = make_float2(ab[kh * 2], ab[kh * 2 + 1]);
    const float* qb = (const float*)&g_qpow[i];
    float2 qp = make_float2(qb[kh * 2], qb[kh * 2 + 1]);

    // S_init = L + G*q^i  (float2 per d-lane)
    const float* Lb = &g_E[(((size_t)b * NCHUNK + c) * D_DIM + dd) * K_DIM + kh * 2];
    const float* Gb = &g_G[(((size_t)b * NGROUP + g) * D_DIM + dd) * K_DIM + kh * 2];
    float2 S0, S1, S2, S3;
    {
        float2 L0 = *(const float2*)(Lb + 0),  G0 = *(const float2*)(Gb + 0);
        float2 L1 = *(const float2*)(Lb + 4),  G1 = *(const float2*)(Gb + 4);
        float2 L2 = *(const float2*)(Lb + 8),  G2 = *(const float2*)(Gb + 8);
        float2 L3 = *(const float2*)(Lb + 12), G3 = *(const float2*)(Gb + 12);
        S0 = make_float2(fmaf(G0.x, qp.x, L0.x), fmaf(G0.y, qp.y, L0.y));
        S1 = make_float2(fmaf(G1.x, qp.x, L1.x), fmaf(G1.y, qp.y, L1.y));
        S2 = make_float2(fmaf(G2.x, qp.x, L2.x), fmaf(G2.y, qp.y, L2.y));
        S3 = make_float2(fmaf(G3.x, qp.x, L3.x), fmaf(G3.y, qp.y, L3.y));
    }

    const float* hp = h + ((size_t)b * T_DIM + (size_t)c * CHUNK_L) * D_DIM + dd;
    float*       op = out + (((size_t)b * T_DIM + (size_t)c * CHUNK_L) * K_DIM + kh * 2) * D_DIM + dd;
    const float* rp = &g_rtab[((size_t)c * CHUNK_L) * K_DIM + kh * 2];

#pragma unroll
    for (int j = 0; j < CHUNK_L; j++) {
        float4 h4 = *(const float4*)(hp + (size_t)j * D_DIM);
        float2 r2 = make_float2(__ldg(rp + j * K_DIM), __ldg(rp + j * K_DIM + 1));

        S0.x = fmaf(a2.x, S0.x, h4.x); S0.y = fmaf(a2.y, S0.y, h4.x);
        S1.x = fmaf(a2.x, S1.x, h4.y); S1.y = fmaf(a2.y, S1.y, h4.y);
        S2.x = fmaf(a2.x, S2.x, h4.z); S2.y = fmaf(a2.y, S2.y, h4.z);
        S3.x = fmaf(a2.x, S3.x, h4.w); S3.y = fmaf(a2.y, S3.y, h4.w);

        float4 olo = make_float4(S0.x * r2.x, S1.x * r2.x, S2.x * r2.x, S3.x * r2.x);
        float4 ohi = make_float4(S0.y * r2.y, S1.y * r2.y, S2.y * r2.y, S3.y * r2.y);

        float* ob = op + (size_t)j * K_DIM * D_DIM;
        __stcs((float4*)(ob + 0 * D_DIM), olo);
        __stcs((float4*)(ob + 1 * D_DIM), ohi);
    }
}

// ---------------------------------------------------------------------------
extern "C" void kernel_launch(void* const* d_in, const int* in_sizes, int n_in,
                              void* d_out, int out_size) {
    const float* h         = (const float*)d_in[0];
    const float* raw_alpha = (const float*)d_in[1];
    int h_elems = in_sizes[0];
    if (n_in >= 2 && in_sizes[1] > in_sizes[0]) {
        h         = (const float*)d_in[1];
        raw_alpha = (const float*)d_in[0];
        h_elems   = in_sizes[1];
    }
    float* out = (float*)d_out;

    int Bn = h_elems / (T_DIM * D_DIM);
    if (Bn > B_MAX) Bn = B_MAX;
    if (Bn < 1)     Bn = 1;

    kA_tables<<<(T_DIM + 255) / 256, 256>>>(raw_alpha);

    { int total = Bn * NCHUNK * (D_DIM / 4);
      kB_chunks<<<(total + 255) / 256, 256>>>(h, Bn); }

    { int total = Bn * NGROUP * D_DIM;
      kC_local<<<(total + 255) / 256, 256>>>(Bn); }

    { int total = Bn * D_DIM;
      kC_global<<<(total + 255) / 256, 256>>>(Bn); }

    kD_final<<<Bn * NCHUNK, 256>>>(h, out, Bn);
}

// round 10
// speedup vs baseline: 1.3062x; 1.0355x over previous
#include <cuda_runtime.h>
#include <math.h>

// h (B=4, T=4096, d=512) fp32, raw_alpha (K=4) fp32 -> out (B, T, K, d) fp32
#define T_DIM 4096
#define D_DIM 512
#define K_DIM 4
#define B_MAX 4
#define CHUNK_L 16
#define NCHUNK (T_DIM / CHUNK_L)   // 256
#define GROUP 16
#define NGROUP (NCHUNK / GROUP)    // 16

// Scratch (allocation-free: __device__ globals)
__device__ float  g_rtab[T_DIM * K_DIM];                    // r[t][k]
__device__ float4 g_alpha4;                                 // alpha
__device__ float4 g_powL4;                                  // q = alpha^16
__device__ float4 g_powLL4;                                 // Q = alpha^256
__device__ float4 g_qpow[GROUP];                            // q^i, i=0..15
__device__ float  g_E[B_MAX * NCHUNK * D_DIM * K_DIM];      // chunk sums -> local carries (8MB)
__device__ float  g_G[B_MAX * NGROUP * D_DIM * K_DIM];      // group sums (512KB)
__device__ float  g_GC[B_MAX * NGROUP * D_DIM * K_DIM];     // group carries (512KB)

__device__ __forceinline__ double sigmoid_clip_d(double x) {
    double a = 1.0 / (1.0 + exp(-x));
    return fmin(fmax(a, 1e-6), 1.0 - 1e-6);
}

// ---------------------------------------------------------------------------
// kA: tables (double precision, one thread per t)
// ---------------------------------------------------------------------------
__global__ void kA_tables(const float* __restrict__ raw_alpha) {
    int t = blockIdx.x * blockDim.x + threadIdx.x;
    if (t >= T_DIM) return;

    double a[K_DIM], la[K_DIM];
#pragma unroll
    for (int k = 0; k < K_DIM; k++) {
        a[k]  = sigmoid_clip_d((double)raw_alpha[k]);
        la[k] = log(a[k]);
    }
#pragma unroll
    for (int k = 0; k < K_DIM; k++) {
        double p = exp(la[k] * (double)(t + 1));
        g_rtab[t * K_DIM + k] = (float)((1.0 - a[k]) / (1.0 - p));
    }
    if (t < GROUP) {   // q^t table
        g_qpow[t] = make_float4((float)exp(la[0] * (double)(CHUNK_L * t)),
                                (float)exp(la[1] * (double)(CHUNK_L * t)),
                                (float)exp(la[2] * (double)(CHUNK_L * t)),
                                (float)exp(la[3] * (double)(CHUNK_L * t)));
    }
    if (t == 0) {
        g_alpha4 = make_float4((float)a[0], (float)a[1], (float)a[2], (float)a[3]);
        g_powL4  = make_float4((float)exp(la[0] * (double)CHUNK_L),
                               (float)exp(la[1] * (double)CHUNK_L),
                               (float)exp(la[2] * (double)CHUNK_L),
                               (float)exp(la[3] * (double)CHUNK_L));
        g_powLL4 = make_float4((float)exp(la[0] * (double)(CHUNK_L * GROUP)),
                               (float)exp(la[1] * (double)(CHUNK_L * GROUP)),
                               (float)exp(la[2] * (double)(CHUNK_L * GROUP)),
                               (float)exp(la[3] * (double)(CHUNK_L * GROUP)));
    }
}

// ---------------------------------------------------------------------------
// kB: per-chunk local scans -> chunk sums E[b][c][dd][k]
// ---------------------------------------------------------------------------
__global__ __launch_bounds__(256) void kB_chunks(const float* __restrict__ h, int Bn) {
    const int DV  = D_DIM / 4;
    int tid = blockIdx.x * blockDim.x + threadIdx.x;
    int ddv = tid % DV;
    int c   = (tid / DV) % NCHUNK;
    int b   = tid / (DV * NCHUNK);
    if (b >= Bn) return;
    int dd = ddv * 4;

    const float4 a4 = g_alpha4;
    float4 S0 = make_float4(0.f, 0.f, 0.f, 0.f);
    float4 S1 = S0, S2 = S0, S3 = S0;

    const float4* hp = (const float4*)(h + ((size_t)b * T_DIM + (size_t)c * CHUNK_L) * D_DIM + dd);

#pragma unroll
    for (int j = 0; j < CHUNK_L; j++) {
        float4 h4 = hp[(size_t)j * DV];
        S0.x = fmaf(a4.x, S0.x, h4.x); S0.y = fmaf(a4.y, S0.y, h4.x);
        S0.z = fmaf(a4.z, S0.z, h4.x); S0.w = fmaf(a4.w, S0.w, h4.x);
        S1.x = fmaf(a4.x, S1.x, h4.y); S1.y = fmaf(a4.y, S1.y, h4.y);
        S1.z = fmaf(a4.z, S1.z, h4.y); S1.w = fmaf(a4.w, S1.w, h4.y);
        S2.x = fmaf(a4.x, S2.x, h4.z); S2.y = fmaf(a4.y, S2.y, h4.z);
        S2.z = fmaf(a4.z, S2.z, h4.z); S2.w = fmaf(a4.w, S2.w, h4.z);
        S3.x = fmaf(a4.x, S3.x, h4.w); S3.y = fmaf(a4.y, S3.y, h4.w);
        S3.z = fmaf(a4.z, S3.z, h4.w); S3.w = fmaf(a4.w, S3.w, h4.w);
    }

    float4* Ep = (float4*)&g_E[(((size_t)b * NCHUNK + c) * D_DIM + dd) * K_DIM];
    Ep[0] = S0; Ep[1] = S1; Ep[2] = S2; Ep[3] = S3;
}

// ---------------------------------------------------------------------------
// kC_local: scan within each group of 16 chunks. In place: E[c] becomes the
// local carry into chunk c (within its group). Emits group sums to g_G.
// ---------------------------------------------------------------------------
__global__ __launch_bounds__(256) void kC_local(int Bn) {
    int tid = blockIdx.x * blockDim.x + threadIdx.x;
    int dd  = tid % D_DIM;
    int g   = (tid / D_DIM) % NGROUP;
    int b   = tid / (D_DIM * NGROUP);
    if (b >= Bn) return;

    const float4 q = g_powL4;
    float4 prev = make_float4(0.f, 0.f, 0.f, 0.f);

#pragma unroll
    for (int i = 0; i < GROUP; i++) {
        int c = g * GROUP + i;
        float4* p = (float4*)&g_E[(((size_t)b * NCHUNK + c) * D_DIM + dd) * K_DIM];
        float4 e = *p;
        *p = prev;
        prev.x = fmaf(q.x, prev.x, e.x);
        prev.y = fmaf(q.y, prev.y, e.y);
        prev.z = fmaf(q.z, prev.z, e.z);
        prev.w = fmaf(q.w, prev.w, e.w);
    }
    *(float4*)&g_G[(((size_t)b * NGROUP + g) * D_DIM + dd) * K_DIM] = prev;
}

// ---------------------------------------------------------------------------
// kC_global: parallel direct carry evaluation. Thread = (b, g, dd):
// carry[g] = sum_{g'<g} Q^{g-1-g'} * s[g']  (Horner, g independent loads).
// Writes to g_GC (separate buffer: no read/write race across threads).
// 32768 threads, 128 blocks.
// ---------------------------------------------------------------------------
__global__ __launch_bounds__(256) void kC_global(int Bn) {
    int tid = blockIdx.x * blockDim.x + threadIdx.x;
    int dd  = tid % D_DIM;
    int g   = (tid / D_DIM) % NGROUP;
    int b   = tid / (D_DIM * NGROUP);
    if (b >= Bn) return;

    const float4 Q = g_powLL4;
    float4 carry = make_float4(0.f, 0.f, 0.f, 0.f);

    for (int gp = 0; gp < g; gp++) {
        float4 s = *(const float4*)&g_G[(((size_t)b * NGROUP + gp) * D_DIM + dd) * K_DIM];
        carry.x = fmaf(Q.x, carry.x, s.x);
        carry.y = fmaf(Q.y, carry.y, s.y);
        carry.z = fmaf(Q.z, carry.z, s.z);
        carry.w = fmaf(Q.w, carry.w, s.w);
    }
    *(float4*)&g_GC[(((size_t)b * NGROUP + g) * D_DIM + dd) * K_DIM] = carry;
}

// ---------------------------------------------------------------------------
// kD: final scan + normalize + store. Split-k: thread = (b, c, kh, dd4),
// 2 k-channels x 4 d-lanes. Block = one (b,c). S_init = L_c + GC_g * q^i.
// ---------------------------------------------------------------------------
__global__ __launch_bounds__(256) void kD_final(const float* __restrict__ h,
                                                float* __restrict__ out, int Bn) {
    int c   = blockIdx.x % NCHUNK;
    int b   = blockIdx.x / NCHUNK;
    if (b >= Bn) return;
    int tid = threadIdx.x;
    int ddv = tid & 127;          // 0..127
    int kh  = tid >> 7;           // 0..1
    int dd  = ddv * 4;
    int g   = c >> 4, i = c & 15;

    const float* ab = (const float*)&g_alpha4;
    float2 a2 = make_float2(ab[kh * 2], ab[kh * 2 + 1]);
    const float* qb = (const float*)&g_qpow[i];
    float2 qp = make_float2(qb[kh * 2], qb[kh * 2 + 1]);

    const float* Lb = &g_E[(((size_t)b * NCHUNK + c) * D_DIM + dd) * K_DIM + kh * 2];
    const float* Gb = &g_GC[(((size_t)b * NGROUP + g) * D_DIM + dd) * K_DIM + kh * 2];
    float2 S0, S1, S2, S3;
    {
        float2 L0 = *(const float2*)(Lb + 0),  G0 = *(const float2*)(Gb + 0);
        float2 L1 = *(const float2*)(Lb + 4),  G1 = *(const float2*)(Gb + 4);
        float2 L2 = *(const float2*)(Lb + 8),  G2 = *(const float2*)(Gb + 8);
        float2 L3 = *(const float2*)(Lb + 12), G3 = *(const float2*)(Gb + 12);
        S0 = make_float2(fmaf(G0.x, qp.x, L0.x), fmaf(G0.y, qp.y, L0.y));
        S1 = make_float2(fmaf(G1.x, qp.x, L1.x), fmaf(G1.y, qp.y, L1.y));
        S2 = make_float2(fmaf(G2.x, qp.x, L2.x), fmaf(G2.y, qp.y, L2.y));
        S3 = make_float2(fmaf(G3.x, qp.x, L3.x), fmaf(G3.y, qp.y, L3.y));
    }

    const float* hp = h + ((size_t)b * T_DIM + (size_t)c * CHUNK_L) * D_DIM + dd;
    float*       op = out + (((size_t)b * T_DIM + (size_t)c * CHUNK_L) * K_DIM + kh * 2) * D_DIM + dd;
    const float* rp = &g_rtab[((size_t)c * CHUNK_L) * K_DIM + kh * 2];

#pragma unroll
    for (int j = 0; j < CHUNK_L; j++) {
        float4 h4 = *(const float4*)(hp + (size_t)j * D_DIM);
        float2 r2 = make_float2(__ldg(rp + j * K_DIM), __ldg(rp + j * K_DIM + 1));

        S0.x = fmaf(a2.x, S0.x, h4.x); S0.y = fmaf(a2.y, S0.y, h4.x);
        S1.x = fmaf(a2.x, S1.x, h4.y); S1.y = fmaf(a2.y, S1.y, h4.y);
        S2.x = fmaf(a2.x, S2.x, h4.z); S2.y = fmaf(a2.y, S2.y, h4.z);
        S3.x = fmaf(a2.x, S3.x, h4.w); S3.y = fmaf(a2.y, S3.y, h4.w);

        float4 olo = make_float4(S0.x * r2.x, S1.x * r2.x, S2.x * r2.x, S3.x * r2.x);
        float4 ohi = make_float4(S0.y * r2.y, S1.y * r2.y, S2.y * r2.y, S3.y * r2.y);

        float* ob = op + (size_t)j * K_DIM * D_DIM;
        __stcs((float4*)(ob + 0 * D_DIM), olo);
        __stcs((float4*)(ob + 1 * D_DIM), ohi);
    }
}

// ---------------------------------------------------------------------------
extern "C" void kernel_launch(void* const* d_in, const int* in_sizes, int n_in,
                              void* d_out, int out_size) {
    const float* h         = (const float*)d_in[0];
    const float* raw_alpha = (const float*)d_in[1];
    int h_elems = in_sizes[0];
    if (n_in >= 2 && in_sizes[1] > in_sizes[0]) {
        h         = (const float*)d_in[1];
        raw_alpha = (const float*)d_in[0];
        h_elems   = in_sizes[1];
    }
    float* out = (float*)d_out;

    int Bn = h_elems / (T_DIM * D_DIM);
    if (Bn > B_MAX) Bn = B_MAX;
    if (Bn < 1)     Bn = 1;

    kA_tables<<<(T_DIM + 255) / 256, 256>>>(raw_alpha);

    { int total = Bn * NCHUNK * (D_DIM / 4);
      kB_chunks<<<(total + 255) / 256, 256>>>(h, Bn); }

    { int total = Bn * NGROUP * D_DIM;
      kC_local<<<(total + 255) / 256, 256>>>(Bn); }

    { int total = Bn * NGROUP * D_DIM;
      kC_global<<<(total + 255) / 256, 256>>>(Bn); }

    kD_final<<<Bn * NCHUNK, 256>>>(h, out, Bn);
}